// round 3
// baseline (speedup 1.0000x reference)
#include <cuda_runtime.h>

#define TPB 256
typedef unsigned long long ull;

// ---------------------------------------------------------------------------
// Precomputed per-run (theta-dependent, batch-invariant):
//   g_W12 : 16x16 complex unitaries for the 12 four-output circuits (A,B,C)
//   g_M   : 16x16 real quadratic forms for the 5 single-output circuits (D,E)
// ---------------------------------------------------------------------------
__device__ __align__(16) float2 g_W12[12 * 256];
__device__ __align__(16) float  g_M[5 * 256];
__device__ __align__(16) float2 g_Wt[5 * 256];   // raw W of circuits 12..16

// theta slice per circuit: A->theta[0], B->theta[3], C->theta[4], D->theta[1], E->theta[2][0]
__device__ __forceinline__ int circ_slice(int c) {
    if (c < 4)  return c;
    if (c < 8)  return 12 + (c - 4);
    if (c < 12) return 16 + (c - 8);
    if (c < 16) return 4 + (c - 12);
    return 8;
}

// Build basis-column `col` of circuit c's 16x16 SEL unitary.
__global__ void build_W(const float* __restrict__ theta) {
    const int c = blockIdx.x, col = threadIdx.x;
    const float* w = theta + circ_slice(c) * 48;
    float sr[16], si[16];
#pragma unroll
    for (int i = 0; i < 16; i++) { sr[i] = (i == col) ? 1.f : 0.f; si[i] = 0.f; }
#pragma unroll
    for (int l = 0; l < 4; l++) {
#pragma unroll
        for (int q = 0; q < 4; q++) {
            const float phi = w[(l * 4 + q) * 3 + 0];
            const float th  = w[(l * 4 + q) * 3 + 1];
            const float om  = w[(l * 4 + q) * 3 + 2];
            float ch, sh, ca, sa, cb, sb;
            __sincosf(0.5f * th, &sh, &ch);
            __sincosf(0.5f * (phi + om), &sa, &ca);
            __sincosf(0.5f * (phi - om), &sb, &cb);
            const float u00r =  ca * ch, u00i = -sa * ch;
            const float u01r = -cb * sh, u01i = -sb * sh;
            const float u10r =  cb * sh, u10i = -sb * sh;
            const float u11r =  ca * ch, u11i =  sa * ch;
            const int mask = 8 >> q;
#pragma unroll
            for (int k = 0; k < 16; k++) {
                if (k & mask) continue;
                const int k1 = k | mask;
                float ar = sr[k],  ai = si[k];
                float br = sr[k1], bi = si[k1];
                sr[k]  = u00r * ar - u00i * ai + u01r * br - u01i * bi;
                si[k]  = u00r * ai + u00i * ar + u01r * bi + u01i * br;
                sr[k1] = u10r * ar - u10i * ai + u11r * br - u11i * bi;
                si[k1] = u10r * ai + u10i * ar + u11r * bi + u11i * br;
            }
        }
        const int r = (l % 3) + 1;
#pragma unroll
        for (int q = 0; q < 4; q++) {
            const int cm = 8 >> q;
            const int tm = 8 >> ((q + r) & 3);
#pragma unroll
            for (int k = 0; k < 16; k++) {
                if ((k & cm) && !(k & tm)) {
                    const int k1 = k | tm;
                    float tr = sr[k], ti = si[k];
                    sr[k] = sr[k1]; si[k] = si[k1];
                    sr[k1] = tr;    si[k1] = ti;
                }
            }
        }
    }
    if (c < 12) {
#pragma unroll
        for (int k = 0; k < 16; k++) g_W12[c * 256 + k * 16 + col] = make_float2(sr[k], si[k]);
    } else {
#pragma unroll
        for (int k = 0; k < 16; k++) g_Wt[(c - 12) * 256 + k * 16 + col] = make_float2(sr[k], si[k]);
    }
}

// Quadratic form M = sum_k s(k) (Wr_k Wr_k^T + Wi_k Wi_k^T), s(k) = +1/-1 on qubit-0 bit.
__global__ void build_M(int dummy) {
    const int c5 = blockIdx.x, r = threadIdx.x;
    float m[16];
#pragma unroll
    for (int j = 0; j < 16; j++) m[j] = 0.f;
#pragma unroll
    for (int k = 0; k < 16; k++) {
        const float2 wr = g_Wt[c5 * 256 + k * 16 + r];
#pragma unroll
        for (int j = 0; j < 16; j++) {
            const float2 wj = g_Wt[c5 * 256 + k * 16 + j];
            const float tt = wr.x * wj.x + wr.y * wj.y;
            m[j] = (k & 8) ? (m[j] - tt) : (m[j] + tt);
        }
    }
#pragma unroll
    for (int j = 0; j < 16; j++) g_M[c5 * 256 + r * 16 + j] = m[j];
}

// ---------------------------------------------------------------------------
// f32x2 packed helpers
// ---------------------------------------------------------------------------
__device__ __forceinline__ ull pk2(float lo, float hi) {
    ull r; asm("mov.b64 %0, {%1, %2};" : "=l"(r) : "f"(lo), "f"(hi)); return r;
}
__device__ __forceinline__ void unpk2(ull v, float& lo, float& hi) {
    asm("mov.b64 {%0, %1}, %2;" : "=f"(lo), "=f"(hi) : "l"(v));
}
__device__ __forceinline__ ull ffma2(ull a, ull b, ull c) {
    ull d; asm("fma.rn.f32x2 %0, %1, %2, %3;" : "=l"(d) : "l"(a), "l"(b), "l"(c)); return d;
}
__device__ __forceinline__ ull fmul2(ull a, ull b) {
    ull d; asm("mul.rn.f32x2 %0, %1, %2;" : "=l"(d) : "l"(a), "l"(b)); return d;
}
__device__ __forceinline__ ull fadd2(ull a, ull b) {
    ull d; asm("add.rn.f32x2 %0, %1, %2;" : "=l"(d) : "l"(a), "l"(b)); return d;
}

__device__ __forceinline__ void emb2(float a0, float a1, float* u) {
    float s0, c0, s1, c1;
    __sincosf(0.5f * a0, &s0, &c0);
    __sincosf(0.5f * a1, &s1, &c1);
    u[0] = c0 * c1; u[1] = c0 * s1; u[2] = s0 * c1; u[3] = s0 * s1;
}

// Walsh tree: p[16] -> 4 signed sums (qubit 0 = MSB of k)
__device__ __forceinline__ void wht4(const float* p, float* o) {
    float a[8], aa[4];
    float e3 = 0.f, e2 = 0.f;
#pragma unroll
    for (int j = 0; j < 8; j++) { a[j] = p[2 * j] + p[2 * j + 1]; e3 += p[2 * j] - p[2 * j + 1]; }
#pragma unroll
    for (int m = 0; m < 4; m++) { aa[m] = a[2 * m] + a[2 * m + 1]; e2 += a[2 * m] - a[2 * m + 1]; }
    o[0] = (aa[0] + aa[1]) - (aa[2] + aa[3]);
    o[1] = (aa[0] - aa[1]) + (aa[2] - aa[3]);
    o[2] = e2;
    o[3] = e3;
}

// Full 4-qubit circuit, 4 expvals.
__device__ __forceinline__ void run4(const ull* __restrict__ W, const float* a, float* o) {
    float u[4], v[4];
    emb2(a[0], a[1], u); emb2(a[2], a[3], v);
    ull pp[16];
#pragma unroll
    for (int i = 0; i < 4; i++)
#pragma unroll
        for (int j = 0; j < 4; j++) { const float t = u[i] * v[j]; pp[i * 4 + j] = pk2(t, t); }
    float p[16];
#pragma unroll
    for (int k = 0; k < 16; k++) {
        const ulonglong2* row = (const ulonglong2*)(W + k * 16);
        const ulonglong2 w0 = row[0], w1 = row[1];
        ull ac0 = fmul2(w0.x, pp[0]), ac2 = fmul2(w0.y, pp[1]);
        ull ac1 = fmul2(w1.x, pp[2]), ac3 = fmul2(w1.y, pp[3]);
#pragma unroll
        for (int jj = 2; jj < 8; jj++) {
            const ulonglong2 w2 = row[jj];
            ac0 = ffma2(w2.x, pp[2 * jj],     (jj & 1) ? ac1 : ac0);
            if (jj & 1) ac1 = ac0;                       // keep 4 chains
        }
        // redo cleanly: simple 4-chain version below replaces the above
        ac0 = fmul2(w0.x, pp[0]); ac2 = fmul2(w0.y, pp[1]);
        ac1 = fmul2(w1.x, pp[2]); ac3 = fmul2(w1.y, pp[3]);
#pragma unroll
        for (int jj = 2; jj < 8; jj += 2) {
            const ulonglong2 wA = row[jj], wB = row[jj + 1];
            ac0 = ffma2(wA.x, pp[2 * jj],     ac0);
            ac2 = ffma2(wA.y, pp[2 * jj + 1], ac2);
            ac1 = ffma2(wB.x, pp[2 * jj + 2], ac1);
            ac3 = ffma2(wB.y, pp[2 * jj + 3], ac3);
        }
        const ull s = fadd2(fadd2(ac0, ac1), fadd2(ac2, ac3));
        float yr, yi; unpk2(s, yr, yi);
        p[k] = fmaf(yr, yr, yi * yi);
    }
    wht4(p, o);
}

// Single expval via real quadratic form e = psi^T M psi.
__device__ __forceinline__ float run1(const float* __restrict__ M, const float* a) {
    float u[4], v[4];
    emb2(a[0], a[1], u); emb2(a[2], a[3], v);
    float psi[16];
#pragma unroll
    for (int i = 0; i < 4; i++)
#pragma unroll
        for (int j = 0; j < 4; j++) psi[i * 4 + j] = u[i] * v[j];
    ull pj[8];
#pragma unroll
    for (int j = 0; j < 8; j++) pj[j] = pk2(psi[2 * j], psi[2 * j + 1]);
    float e = 0.f;
#pragma unroll
    for (int k = 0; k < 16; k++) {
        const ulonglong2* row = (const ulonglong2*)(M + k * 16);
        const ulonglong2 m0 = row[0], m1 = row[1], m2 = row[2], m3 = row[3];
        ull a0c = fmul2(m0.x, pj[0]);
        ull a1c = fmul2(m0.y, pj[1]);
        a0c = ffma2(m1.x, pj[2], a0c);
        a1c = ffma2(m1.y, pj[3], a1c);
        a0c = ffma2(m2.x, pj[4], a0c);
        a1c = ffma2(m2.y, pj[5], a1c);
        a0c = ffma2(m3.x, pj[6], a0c);
        a1c = ffma2(m3.y, pj[7], a1c);
        const ull s = fadd2(a0c, a1c);
        float lo, hi; unpk2(s, lo, hi);
        e = fmaf(psi[k], lo + hi, e);
    }
    return e;
}

// ---------------------------------------------------------------------------
// Main kernel: 4 threads per batch element (one circuit per thread per stage),
// 4x4 smem transposes between stages. Uniform control flow.
// ---------------------------------------------------------------------------
__global__ __launch_bounds__(TPB, 2)
void vqc_main4(const float* __restrict__ x, float* __restrict__ out, int B) {
    __shared__ __align__(16) ull   sW[12 * 256];     // 24 KB
    __shared__ __align__(16) float sM[5 * 256];      // 5 KB
    __shared__ __align__(16) float xch[TPB / 4][20]; // padded: stride 20 => conflict-free

    const int tid = threadIdx.x;
    {   // cooperative smem fill from L2
        const float4* srcW = (const float4*)g_W12;
        float4* dstW = (float4*)sW;
        for (int i = tid; i < 12 * 256 * 8 / 16; i += TPB) dstW[i] = srcW[i];
        const float4* srcM = (const float4*)g_M;
        float4* dstM = (float4*)sM;
        for (int i = tid; i < 5 * 256 * 4 / 16; i += TPB) dstM[i] = srcM[i];
    }
    __syncthreads();

    const int g   = tid >> 2;                         // group within block
    const int t   = tid & 3;                          // lane role 0..3
    int grp = blockIdx.x * (TPB / 4) + g;             // batch element
    const bool live = grp < B;
    if (!live) grp = B - 1;

    // Stage-A angles: H = [0, x0..x12, 0, 0]; circuit t uses H[4t..4t+3]
    float a[4];
    const float* xb = x + (long)grp * 13;
#pragma unroll
    for (int i = 0; i < 4; i++) {
        const int j = 4 * t + i;
        a[i] = (j >= 1 && j < 14) ? xb[j - 1] : 0.f;
    }

    float o[4];
    // Stage A
    run4(sW + t * 256, a, o);
    __syncwarp();
    *(float4*)&xch[g][t * 4] = make_float4(o[0], o[1], o[2], o[3]);
    __syncwarp();
#pragma unroll
    for (int i = 0; i < 4; i++) a[i] = xch[g][i * 4 + t];
    // Stage B
    run4(sW + (4 + t) * 256, a, o);
    __syncwarp();
    *(float4*)&xch[g][t * 4] = make_float4(o[0], o[1], o[2], o[3]);
    __syncwarp();
#pragma unroll
    for (int i = 0; i < 4; i++) a[i] = xch[g][i * 4 + t];
    // Stage C
    run4(sW + (8 + t) * 256, a, o);
    __syncwarp();
    *(float4*)&xch[g][t * 4] = make_float4(o[0], o[1], o[2], o[3]);
    __syncwarp();
#pragma unroll
    for (int i = 0; i < 4; i++) a[i] = xch[g][i * 4 + t];
    // Stage D: one expval per thread
    const float h4 = run1(sM + t * 256, a);
    __syncwarp();
    xch[g][t] = h4;
    __syncwarp();
#pragma unroll
    for (int i = 0; i < 4; i++) a[i] = xch[g][i];
    // Stage E (redundant on all 4 lanes; lane 0 writes)
    const float e = run1(sM + 4 * 256, a);
    if (t == 0 && live)
        out[grp] = e * (float)(3.141592653589793 - 1.1920928955078125e-7);
}

extern "C" void kernel_launch(void* const* d_in, const int* in_sizes, int n_in,
                              void* d_out, int out_size) {
    const float* x     = (const float*)d_in[0];
    const float* theta = (const float*)d_in[1];
    if (n_in >= 2 && in_sizes[0] < in_sizes[1]) {
        x     = (const float*)d_in[1];
        theta = (const float*)d_in[0];
    }
    float* out = (float*)d_out;
    const int B = out_size;

    build_W<<<17, 16>>>(theta);
    build_M<<<5, 16>>>(0);
    const int groups_per_block = TPB / 4;
    vqc_main4<<<(B + groups_per_block - 1) / groups_per_block, TPB>>>(x, out, B);
}

// round 5
// speedup vs baseline: 3.6940x; 3.6940x over previous
#include <cuda_runtime.h>

#define TPB 128
typedef unsigned long long ull;

// Precomputed (theta-dependent, batch-invariant)
__device__ __align__(16) float2 g_W12[12 * 256];   // unitaries, circuits 0..11 (stages A,B,C)
__device__ __align__(16) float  g_M[5 * 256];      // quadratic forms, circuits 12..16 (D,E)

// theta slice per circuit: A->theta[0], B->theta[3], C->theta[4], D->theta[1], E->theta[2][0]
__device__ __forceinline__ int circ_slice(int c) {
    if (c < 4)  return c;
    if (c < 8)  return 12 + (c - 4);
    if (c < 12) return 16 + (c - 8);
    if (c < 16) return 4 + (c - 12);
    return 8;
}

// One block per circuit (16 threads = 16 basis columns). For circuits 12..16 the
// block additionally reduces W -> M (real quadratic form) through shared memory.
__global__ void build_WM(const float* __restrict__ theta) {
    const int c = blockIdx.x, col = threadIdx.x;
    const float* w = theta + circ_slice(c) * 48;

    float sr[16], si[16];
#pragma unroll
    for (int i = 0; i < 16; i++) { sr[i] = (i == col) ? 1.f : 0.f; si[i] = 0.f; }
#pragma unroll
    for (int l = 0; l < 4; l++) {
#pragma unroll
        for (int q = 0; q < 4; q++) {
            const float phi = w[(l * 4 + q) * 3 + 0];
            const float th  = w[(l * 4 + q) * 3 + 1];
            const float om  = w[(l * 4 + q) * 3 + 2];
            float ch, sh, ca, sa, cb, sb;
            __sincosf(0.5f * th, &sh, &ch);
            __sincosf(0.5f * (phi + om), &sa, &ca);
            __sincosf(0.5f * (phi - om), &sb, &cb);
            const float u00r =  ca * ch, u00i = -sa * ch;
            const float u01r = -cb * sh, u01i = -sb * sh;
            const float u10r =  cb * sh, u10i = -sb * sh;
            const float u11r =  ca * ch, u11i =  sa * ch;
            const int mask = 8 >> q;
#pragma unroll
            for (int k = 0; k < 16; k++) {
                if (k & mask) continue;
                const int k1 = k | mask;
                float ar = sr[k],  ai = si[k];
                float br = sr[k1], bi = si[k1];
                sr[k]  = u00r * ar - u00i * ai + u01r * br - u01i * bi;
                si[k]  = u00r * ai + u00i * ar + u01r * bi + u01i * br;
                sr[k1] = u10r * ar - u10i * ai + u11r * br - u11i * bi;
                si[k1] = u10r * ai + u10i * ar + u11r * bi + u11i * br;
            }
        }
        const int r = (l % 3) + 1;
#pragma unroll
        for (int q = 0; q < 4; q++) {
            const int cm = 8 >> q;
            const int tm = 8 >> ((q + r) & 3);
#pragma unroll
            for (int k = 0; k < 16; k++) {
                if ((k & cm) && !(k & tm)) {
                    const int k1 = k | tm;
                    float tr = sr[k], ti = si[k];
                    sr[k] = sr[k1]; si[k] = si[k1];
                    sr[k1] = tr;    si[k1] = ti;
                }
            }
        }
    }

    if (c < 12) {
#pragma unroll
        for (int k = 0; k < 16; k++)
            g_W12[c * 256 + k * 16 + col] = make_float2(sr[k], si[k]);
    } else {
        __shared__ float2 sWt[256];
#pragma unroll
        for (int k = 0; k < 16; k++) sWt[k * 16 + col] = make_float2(sr[k], si[k]);
        __syncthreads();
        const int r = col;
        float m[16];
#pragma unroll
        for (int j = 0; j < 16; j++) m[j] = 0.f;
#pragma unroll
        for (int k = 0; k < 16; k++) {
            const float2 wr = sWt[k * 16 + r];
#pragma unroll
            for (int j = 0; j < 16; j++) {
                const float2 wj = sWt[k * 16 + j];
                const float tt = wr.x * wj.x + wr.y * wj.y;
                m[j] = (k & 8) ? (m[j] - tt) : (m[j] + tt);
            }
        }
#pragma unroll
        for (int j = 0; j < 16; j++) g_M[(c - 12) * 256 + r * 16 + j] = m[j];
    }
}

// ---------------------------------------------------------------------------
// f32x2 packed helpers
// ---------------------------------------------------------------------------
__device__ __forceinline__ ull pk2(float lo, float hi) {
    ull r; asm("mov.b64 %0, {%1, %2};" : "=l"(r) : "f"(lo), "f"(hi)); return r;
}
__device__ __forceinline__ void unpk2(ull v, float& lo, float& hi) {
    asm("mov.b64 {%0, %1}, %2;" : "=f"(lo), "=f"(hi) : "l"(v));
}
__device__ __forceinline__ ull ffma2(ull a, ull b, ull c) {
    ull d; asm("fma.rn.f32x2 %0, %1, %2, %3;" : "=l"(d) : "l"(a), "l"(b), "l"(c)); return d;
}
__device__ __forceinline__ ull fmul2(ull a, ull b) {
    ull d; asm("mul.rn.f32x2 %0, %1, %2;" : "=l"(d) : "l"(a), "l"(b)); return d;
}
__device__ __forceinline__ ull fadd2(ull a, ull b) {
    ull d; asm("add.rn.f32x2 %0, %1, %2;" : "=l"(d) : "l"(a), "l"(b)); return d;
}

__device__ __forceinline__ void emb2(float a0, float a1, float* u) {
    float s0, c0, s1, c1;
    __sincosf(0.5f * a0, &s0, &c0);
    __sincosf(0.5f * a1, &s1, &c1);
    u[0] = c0 * c1; u[1] = c0 * s1; u[2] = s0 * c1; u[3] = s0 * s1;
}

// Walsh tree: p[16] -> 4 signed sums (qubit 0 = MSB of k)
__device__ __forceinline__ void wht4(const float* p, float* o) {
    float a[8], aa[4];
    float e3 = 0.f, e2 = 0.f;
#pragma unroll
    for (int j = 0; j < 8; j++) { a[j] = p[2 * j] + p[2 * j + 1]; e3 += p[2 * j] - p[2 * j + 1]; }
#pragma unroll
    for (int m = 0; m < 4; m++) { aa[m] = a[2 * m] + a[2 * m + 1]; e2 += a[2 * m] - a[2 * m + 1]; }
    o[0] = (aa[0] + aa[1]) - (aa[2] + aa[3]);
    o[1] = (aa[0] - aa[1]) + (aa[2] - aa[3]);
    o[2] = e2;
    o[3] = e3;
}

// Full circuit, 4 expvals. W rows packed as f32x2 complex.
__device__ __forceinline__ void run4_full(const ull* __restrict__ W,
                                          float a0, float a1, float a2, float a3,
                                          float* o) {
    float u[4], v[4];
    emb2(a0, a1, u); emb2(a2, a3, v);
    ull pp[16];
#pragma unroll
    for (int i = 0; i < 4; i++)
#pragma unroll
        for (int j = 0; j < 4; j++) { const float t = u[i] * v[j]; pp[i * 4 + j] = pk2(t, t); }
    float p[16];
#pragma unroll 4
    for (int k = 0; k < 16; k++) {
        const ulonglong2* row = (const ulonglong2*)(W + k * 16);
        const ulonglong2 w0 = row[0], w1 = row[1];
        ull ac0 = fmul2(w0.x, pp[0]), ac2 = fmul2(w0.y, pp[1]);
        ull ac1 = fmul2(w1.x, pp[2]), ac3 = fmul2(w1.y, pp[3]);
#pragma unroll
        for (int jj = 2; jj < 8; jj += 2) {
            const ulonglong2 wA = row[jj], wB = row[jj + 1];
            ac0 = ffma2(wA.x, pp[2 * jj],     ac0);
            ac2 = ffma2(wA.y, pp[2 * jj + 1], ac2);
            ac1 = ffma2(wB.x, pp[2 * jj + 2], ac1);
            ac3 = ffma2(wB.y, pp[2 * jj + 3], ac3);
        }
        const ull s = fadd2(fadd2(ac0, ac1), fadd2(ac2, ac3));
        float yr, yi; unpk2(s, yr, yi);
        p[k] = fmaf(yr, yr, yi * yi);
    }
    wht4(p, o);
}

// a0 == 0 : only columns 0..7 active
__device__ __forceinline__ void run4_half(const ull* __restrict__ W,
                                          float a1, float a2, float a3, float* o) {
    float s1, c1, v[4];
    __sincosf(0.5f * a1, &s1, &c1);
    emb2(a2, a3, v);
    ull pp[8];
#pragma unroll
    for (int j = 0; j < 4; j++) {
        const float t0 = c1 * v[j], t1 = s1 * v[j];
        pp[j] = pk2(t0, t0); pp[4 + j] = pk2(t1, t1);
    }
    float p[16];
#pragma unroll 4
    for (int k = 0; k < 16; k++) {
        const ulonglong2* row = (const ulonglong2*)(W + k * 16);
        const ulonglong2 w0 = row[0], w1 = row[1], w2 = row[2], w3 = row[3];
        ull a0c = fmul2(w0.x, pp[0]);
        ull a1c = fmul2(w0.y, pp[1]);
        a0c = ffma2(w1.x, pp[2], a0c);
        a1c = ffma2(w1.y, pp[3], a1c);
        a0c = ffma2(w2.x, pp[4], a0c);
        a1c = ffma2(w2.y, pp[5], a1c);
        a0c = ffma2(w3.x, pp[6], a0c);
        a1c = ffma2(w3.y, pp[7], a1c);
        const ull s = fadd2(a0c, a1c);
        float yr, yi; unpk2(s, yr, yi);
        p[k] = fmaf(yr, yr, yi * yi);
    }
    wht4(p, o);
}

// a2 == a3 == 0 : only columns {0,4,8,12} active
__device__ __forceinline__ void run4_sparse(const ull* __restrict__ W,
                                            float a0, float a1, float* o) {
    float u[4];
    emb2(a0, a1, u);
    ull pu[4];
#pragma unroll
    for (int i = 0; i < 4; i++) pu[i] = pk2(u[i], u[i]);
    float p[16];
#pragma unroll 4
    for (int k = 0; k < 16; k++) {
        const ull* row = W + k * 16;
        ull a0c = fmul2(row[0], pu[0]);
        ull a1c = fmul2(row[4], pu[1]);
        a0c = ffma2(row[8],  pu[2], a0c);
        a1c = ffma2(row[12], pu[3], a1c);
        const ull s = fadd2(a0c, a1c);
        float yr, yi; unpk2(s, yr, yi);
        p[k] = fmaf(yr, yr, yi * yi);
    }
    wht4(p, o);
}

// Single expval via real quadratic form e = psi^T M psi.
__device__ __forceinline__ float run1(const float* __restrict__ M,
                                      float a0, float a1, float a2, float a3) {
    float u[4], v[4];
    emb2(a0, a1, u); emb2(a2, a3, v);
    float psi[16];
#pragma unroll
    for (int i = 0; i < 4; i++)
#pragma unroll
        for (int j = 0; j < 4; j++) psi[i * 4 + j] = u[i] * v[j];
    ull pj[8];
#pragma unroll
    for (int j = 0; j < 8; j++) pj[j] = pk2(psi[2 * j], psi[2 * j + 1]);
    float e = 0.f;
#pragma unroll
    for (int k = 0; k < 16; k++) {
        const ulonglong2* row = (const ulonglong2*)(M + k * 16);
        const ulonglong2 m0 = row[0], m1 = row[1], m2 = row[2], m3 = row[3];
        ull a0c = fmul2(m0.x, pj[0]);
        ull a1c = fmul2(m0.y, pj[1]);
        a0c = ffma2(m1.x, pj[2], a0c);
        a1c = ffma2(m1.y, pj[3], a1c);
        a0c = ffma2(m2.x, pj[4], a0c);
        a1c = ffma2(m2.y, pj[5], a1c);
        a0c = ffma2(m3.x, pj[6], a0c);
        a1c = ffma2(m3.y, pj[7], a1c);
        const ull s = fadd2(a0c, a1c);
        float lo, hi; unpk2(s, lo, hi);
        e = fmaf(psi[k], lo + hi, e);
    }
    return e;
}

// ---------------------------------------------------------------------------
// Main kernel: one thread per batch element (proven R1 layout).
// ---------------------------------------------------------------------------
__global__ __launch_bounds__(TPB)
void vqc_main(const float* __restrict__ x, float* __restrict__ out, int B) {
    __shared__ __align__(16) ull   sW[12 * 256];   // 24 KB
    __shared__ __align__(16) float sM[5 * 256];    // 5 KB
    {
        const int tid = threadIdx.x;
        const float4* srcW = (const float4*)g_W12;
        float4* dstW = (float4*)sW;
        for (int i = tid; i < 12 * 128; i += TPB) dstW[i] = srcW[i];
        const float4* srcM = (const float4*)g_M;
        float4* dstM = (float4*)sM;
        for (int i = tid; i < 5 * 64; i += TPB) dstM[i] = srcM[i];
    }
    __syncthreads();

    const int b = blockIdx.x * TPB + threadIdx.x;
    if (b >= B) return;

    float H[16], Hn[16], H4[4];
#pragma unroll
    for (int i = 0; i < 13; i++) H[1 + i] = x[b * 13 + i];

    // Stage A (H[0]=0 -> half; H[14]=H[15]=0 -> sparse)
    run4_half  (sW + 0 * 256, H[1], H[2], H[3], &Hn[0]);
    run4_full  (sW + 1 * 256, H[4], H[5], H[6], H[7],   &Hn[4]);
    run4_full  (sW + 2 * 256, H[8], H[9], H[10], H[11], &Hn[8]);
    run4_sparse(sW + 3 * 256, H[12], H[13], &Hn[12]);
    // Stage B (transposed wiring) Hn -> H
#pragma unroll
    for (int j = 0; j < 4; j++)
        run4_full(sW + (4 + j) * 256, Hn[j], Hn[4 + j], Hn[8 + j], Hn[12 + j], &H[4 * j]);
    // Stage C: H -> Hn
#pragma unroll
    for (int j = 0; j < 4; j++)
        run4_full(sW + (8 + j) * 256, H[j], H[4 + j], H[8 + j], H[12 + j], &Hn[4 * j]);
    // Stage D: 16 -> 4 via quadratic forms
#pragma unroll
    for (int j = 0; j < 4; j++)
        H4[j] = run1(sM + j * 256, Hn[j], Hn[4 + j], Hn[8 + j], Hn[12 + j]);
    // Stage E: 4 -> 1
    const float o = run1(sM + 4 * 256, H4[0], H4[1], H4[2], H4[3]);

    out[b] = o * (float)(3.141592653589793 - 1.1920928955078125e-7);
}

extern "C" void kernel_launch(void* const* d_in, const int* in_sizes, int n_in,
                              void* d_out, int out_size) {
    const float* x     = (const float*)d_in[0];
    const float* theta = (const float*)d_in[1];
    if (n_in >= 2 && in_sizes[0] < in_sizes[1]) {
        x     = (const float*)d_in[1];
        theta = (const float*)d_in[0];
    }
    float* out = (float*)d_out;
    const int B = out_size;

    build_WM<<<17, 16>>>(theta);
    vqc_main<<<(B + TPB - 1) / TPB, TPB>>>(x, out, B);
}